// round 6
// baseline (speedup 1.0000x reference)
#include <cuda_runtime.h>

#define B_ 2
#define N_ 4096
#define M_ 4096
#define K_ 2048
#define NN 8192          // B_*N_ flattened points
#define KTOP 50
#define CAND_CAP 2048

static __device__ unsigned g_min_pg[B_*N_];   // min over gt for each pred
static __device__ unsigned g_min_gp[B_*M_];   // min over pred for each gt
static __device__ unsigned g_min_cov[B_*K_];  // min over pred for each partial
static __device__ double   g_acc[8];          // 0:cham1 1:cham2 2:cov 3:emd 4:unif 5:spread 6:rep
static __device__ float4   g_pts4[NN];        // packed pred points for uniformity
static __device__ float    g_sortP[3*NN];
static __device__ float    g_sortG[3*NN];

// ---------------------------------------------------------------- helpers
__device__ __forceinline__ void block_add_to_acc(float v, int slot) {
    for (int o = 16; o; o >>= 1) v += __shfl_xor_sync(0xFFFFFFFFu, v, o);
    __shared__ float sw[32];
    int lane = threadIdx.x & 31, wid = threadIdx.x >> 5;
    if (lane == 0) sw[wid] = v;
    __syncthreads();
    if (threadIdx.x == 0) {
        float s = 0.f;
        int nw = (blockDim.x + 31) >> 5;
        for (int w = 0; w < nw; w++) s += sw[w];
        atomicAdd(&g_acc[slot], (double)s);
    }
}

__device__ __forceinline__ unsigned* min_sel(int which) {
    return which == 0 ? g_min_pg : (which == 1 ? g_min_gp : g_min_cov);
}

// ---------------------------------------------------------------- init
__global__ void init_kernel() {
    int i = blockIdx.x * 256 + threadIdx.x;
    if (i < B_*N_) g_min_pg[i]  = 0x7F800000u;
    if (i < B_*M_) g_min_gp[i]  = 0x7F800000u;
    if (i < B_*K_) g_min_cov[i] = 0x7F800000u;
    if (i < 8)     g_acc[i] = 0.0;
}

__global__ void pack_kernel(const float* __restrict__ pred) {
    int i = blockIdx.x * 256 + threadIdx.x;
    if (i < NN) g_pts4[i] = make_float4(pred[3*i], pred[3*i+1], pred[3*i+2], 0.f);
}

// ---------------------------------------------------------------- row-min pairwise sq dist
__global__ void rowmin_kernel(const float* __restrict__ A, const float* __restrict__ Bp,
                              int nA, int nB, int chunk, int which) {
    __shared__ float4 sb[128];
    int b = blockIdx.z;
    const float* Ab = A  + (size_t)b * nA * 3;
    const float* Bb = Bp + ((size_t)b * nB + (size_t)blockIdx.y * chunk) * 3;
    int i = blockIdx.x * 128 + threadIdx.x;
    float ax = Ab[3*i], ay = Ab[3*i+1], az = Ab[3*i+2];
    float best0 = __int_as_float(0x7F800000);
    float best1 = best0;
    for (int t = 0; t < chunk; t += 128) {
        __syncthreads();
        const float* src = Bb + 3*(t + threadIdx.x);
        sb[threadIdx.x] = make_float4(src[0], src[1], src[2], 0.f);
        __syncthreads();
#pragma unroll 16
        for (int j = 0; j < 128; j += 2) {
            float4 q0 = sb[j], q1 = sb[j+1];
            float dx0 = ax - q0.x, dy0 = ay - q0.y, dz0 = az - q0.z;
            float dx1 = ax - q1.x, dy1 = ay - q1.y, dz1 = az - q1.z;
            float dd0 = fmaf(dx0, dx0, fmaf(dy0, dy0, dz0*dz0));
            float dd1 = fmaf(dx1, dx1, fmaf(dy1, dy1, dz1*dz1));
            best0 = fminf(best0, dd0);
            best1 = fminf(best1, dd1);
        }
    }
    float best = fminf(best0, best1);
    atomicMin(&min_sel(which)[b*nA + i], __float_as_uint(best));
}

__global__ void summin_kernel(int which, int n, int do_sqrt, int slot) {
    int i = blockIdx.x * 256 + threadIdx.x;
    float v = 0.f;
    if (i < n) {
        v = __uint_as_float(min_sel(which)[i]);
        if (do_sqrt) v = sqrtf(v);
    }
    block_add_to_acc(v, slot);
}

// ---------------------------------------------------------------- EMD: bitonic column sort
__global__ void emd_sort_kernel(const float* __restrict__ pred, const float* __restrict__ gt) {
    __shared__ float a[NN];
    int which = blockIdx.x;           // 0..5
    int c = which % 3;
    const float* src = (which < 3) ? pred : gt;
    float* dst = (which < 3) ? (g_sortP + c*NN) : (g_sortG + c*NN);
    int tid = threadIdx.x;
    for (int i = tid; i < NN; i += 1024) a[i] = src[3*i + c];
    __syncthreads();
    for (int k = 2; k <= NN; k <<= 1)
        for (int j = k >> 1; j > 0; j >>= 1) {
            for (int i = tid; i < NN; i += 1024) {
                int ixj = i ^ j;
                if (ixj > i) {
                    float x = a[i], y = a[ixj];
                    bool up = ((i & k) == 0);
                    if ((x > y) == up) { a[i] = y; a[ixj] = x; }
                }
            }
            __syncthreads();
        }
    for (int i = tid; i < NN; i += 1024) dst[i] = a[i];
}

__global__ void emd_diff_kernel() {
    int i = blockIdx.x * 256 + threadIdx.x;
    float v = 0.f;
    if (i < 3*NN) { float d = g_sortP[i] - g_sortG[i]; v = d*d; }
    block_add_to_acc(v, 3);
}

// ---------------------------------------------------------------- uniformity: per-row 50-NN std
// Block handles 32 rows, 2 per pass sharing q loads; distances stay in registers.
// Selection: speculative power-of-2 threshold gather (adaptive guess, retry from
// registers if count < KTOP) -> exact parallel rank-by-count over candidates.
#define PROCESS_ROW(DD)                                                          \
    {                                                                            \
        __syncthreads();                /* s_guess/s_buf ready */                 \
        int E = s_guess; int cnt;                                                \
        for (;;) {                                                               \
            if (tid == 0) s_cnt = 0;                                             \
            __syncthreads();                                                     \
            float Tf = __uint_as_float((unsigned)(E + 1) << 23);                 \
            _Pragma("unroll")                                                    \
            for (int k = 0; k < 32; k++) {                                       \
                float v = DD[k];                                                 \
                if (v < Tf) {                                                    \
                    unsigned pos = atomicAdd(&s_cnt, 1u);                        \
                    if (pos < CAND_CAP) s_buf[pos] = v;                          \
                }                                                                \
            }                                                                    \
            __syncthreads();                                                     \
            cnt = (int)s_cnt;                                                    \
            __syncthreads();                                                     \
            if (cnt >= KTOP) break;                                              \
            E += (cnt < 8) ? 4 : ((cnt < 25) ? 2 : 1);                           \
        }                                                                        \
        int c = min(cnt, CAND_CAP);                                              \
        float t1 = 0.f, t2 = 0.f;                                                \
        for (int j = tid; j < c; j += 256) {                                     \
            float v = s_buf[j];                                                  \
            int rank = 0;                                                        \
            for (int k = 0; k < c; k++) {                                        \
                float w = s_buf[k];                                              \
                rank += (w < v) || (w == v && k < j);                            \
            }                                                                    \
            if (rank >= 1 && rank < KTOP) { t1 += sqrtf(v); t2 += v; }           \
        }                                                                        \
        for (int o = 16; o; o >>= 1) {                                           \
            t1 += __shfl_xor_sync(0xFFFFFFFFu, t1, o);                           \
            t2 += __shfl_xor_sync(0xFFFFFFFFu, t2, o);                           \
        }                                                                        \
        if (lane == 0) { s_r1[wid] = t1; s_r2[wid] = t2; }                       \
        __syncthreads();                                                         \
        if (tid == 0) {                                                          \
            double s1 = 0.0, s2 = 0.0;                                           \
            for (int w = 0; w < 8; w++) { s1 += (double)s_r1[w]; s2 += (double)s_r2[w]; } \
            double mean = s1 / 49.0;                                             \
            double var = (s2 - 49.0*mean*mean) / 48.0;                           \
            if (var < 0.0) var = 0.0;                                            \
            rowacc += sqrt(var);                                                 \
            s_guess = E - ((cnt > 320) ? 2 : ((cnt > 160) ? 1 : 0));             \
        }                                                                        \
    }

__global__ void __launch_bounds__(256) uniformity_kernel() {
    __shared__ float    s_buf[CAND_CAP];
    __shared__ unsigned s_cnt;
    __shared__ int      s_guess;
    __shared__ float    s_r1[8], s_r2[8];
    int tid = threadIdx.x, lane = tid & 31, wid = tid >> 5;
    double rowacc = 0.0;   // meaningful only on tid==0
    if (tid == 0) s_guess = 112;   // ~3e-5: well below any 50NN radius; warms up fast

    for (int r = 0; r < 32; r += 2) {
        int row = blockIdx.x * 32 + r;
        float4 p0 = g_pts4[row], p1 = g_pts4[row + 1];

        float d0[32], d1[32];
#pragma unroll
        for (int k = 0; k < 32; k++) {
            float4 q = g_pts4[k*256 + tid];
            float dx0 = p0.x - q.x, dy0 = p0.y - q.y, dz0 = p0.z - q.z;
            float dx1 = p1.x - q.x, dy1 = p1.y - q.y, dz1 = p1.z - q.z;
            d0[k] = fmaf(dx0, dx0, fmaf(dy0, dy0, dz0*dz0));
            d1[k] = fmaf(dx1, dx1, fmaf(dy1, dy1, dz1*dz1));
        }

        PROCESS_ROW(d0)
        PROCESS_ROW(d1)
    }
    if (tid == 0) atomicAdd(&g_acc[4], rowacc);
}

// ---------------------------------------------------------------- spread
__global__ void spread_kernel(const float* __restrict__ pred) {
    int b = blockIdx.x / 3, c = blockIdx.x % 3;
    const float* p = pred + (size_t)b * N_ * 3 + c;
    double s1 = 0.0, s2 = 0.0;
    for (int i = threadIdx.x; i < N_; i += 256) {
        double x = (double)p[3*i];
        s1 += x; s2 += x*x;
    }
    for (int o = 16; o; o >>= 1) {
        s1 += __shfl_xor_sync(0xFFFFFFFFu, s1, o);
        s2 += __shfl_xor_sync(0xFFFFFFFFu, s2, o);
    }
    __shared__ double sw1[8], sw2[8];
    int lane = threadIdx.x & 31, wid = threadIdx.x >> 5;
    if (lane == 0) { sw1[wid] = s1; sw2[wid] = s2; }
    __syncthreads();
    if (threadIdx.x == 0) {
        double a = 0, bb = 0;
        for (int w = 0; w < 8; w++) { a += sw1[w]; bb += sw2[w]; }
        double mean = a / (double)N_;
        double var = (bb - (double)N_ * mean * mean) / (double)(N_ - 1);
        if (var < 0.0) var = 0.0;
        atomicAdd(&g_acc[5], sqrt(var));
    }
}

// ---------------------------------------------------------------- repulsion
// NOTE: sample_idx arrives as int32 (JAX x64 disabled downcasts astype(int64)).
__global__ void repulsion_kernel(const float* __restrict__ pred,
                                 const int* __restrict__ sidx) {
    __shared__ float sp[200*3];
    int tid = threadIdx.x;
    for (int s = tid; s < 200; s += 256) {
        int b = s / 100, k = s % 100;
        int idx = sidx[k];
        if (idx < 0) idx = 0;
        if (idx >= N_) idx = N_ - 1;
        const float* src = pred + ((size_t)b * N_ + (size_t)idx) * 3;
        sp[3*s] = src[0]; sp[3*s+1] = src[1]; sp[3*s+2] = src[2];
    }
    __syncthreads();
    float sum = 0.f;
    for (int t = tid; t < 2*100*100; t += 256) {
        int b = t / 10000, rem = t % 10000, i = rem / 100, j = rem % 100;
        if (i != j) {
            const float* pi = &sp[(b*100 + i)*3];
            const float* pj = &sp[(b*100 + j)*3];
            float dx = pi[0]-pj[0], dy = pi[1]-pj[1], dz = pi[2]-pj[2];
            float dd = fmaf(dx, dx, fmaf(dy, dy, dz*dz));
            float rr = 0.01f - sqrtf(dd);
            if (rr > 0.f) sum += rr;
        }
    }
    block_add_to_acc(sum, 6);
}

// ---------------------------------------------------------------- finalize
__global__ void final_kernel(float* out) {
    double cham   = g_acc[0] / (double)(B_*N_) + g_acc[1] / (double)(B_*M_);
    double emd    = g_acc[3] / (double)(NN*3) * 0.1;
    double cov    = g_acc[2] / (double)(B_*K_) * 5.0;
    double unif   = g_acc[4] / (double)NN * 2.0;
    double sstd   = g_acc[5] / 6.0;
    double spread = 0.5 - sstd;
    spread = (spread > 0.0) ? spread * 10.0 : 0.0;
    double rep    = g_acc[6] / (double)(B_*100*100) * 5.0;
    out[0] = (float)(cham + emd + cov + unif + spread + rep);
}

// ---------------------------------------------------------------- launch (serial: each big
// kernel fills the chip; multi-stream measured as a regression in R5)
extern "C" void kernel_launch(void* const* d_in, const int* in_sizes, int n_in,
                              void* d_out, int out_size) {
    const float* pred    = (const float*)d_in[0];
    const float* gt      = (const float*)d_in[1];
    const float* partial = (const float*)d_in[2];
    const int*   sidx    = (const int*)d_in[3];
    float* out = (float*)d_out;

    init_kernel<<<32, 256>>>();
    pack_kernel<<<32, 256>>>(pred);

    uniformity_kernel<<<NN/32, 256>>>();

    rowmin_kernel<<<dim3(N_/128, 16, B_), 128>>>(pred, gt,   N_, M_, M_/16, 0);
    rowmin_kernel<<<dim3(M_/128, 16, B_), 128>>>(gt,   pred, M_, N_, N_/16, 1);
    rowmin_kernel<<<dim3(K_/128, 16, B_), 128>>>(partial, pred, K_, N_, N_/16, 2);

    summin_kernel<<<(B_*N_+255)/256, 256>>>(0, B_*N_, 0, 0);
    summin_kernel<<<(B_*M_+255)/256, 256>>>(1, B_*M_, 0, 1);
    summin_kernel<<<(B_*K_+255)/256, 256>>>(2, B_*K_, 1, 2);

    emd_sort_kernel<<<6, 1024>>>(pred, gt);
    emd_diff_kernel<<<(3*NN+255)/256, 256>>>();

    spread_kernel<<<6, 256>>>(pred);
    repulsion_kernel<<<1, 256>>>(pred, sidx);

    final_kernel<<<1, 1>>>(out);
}

// round 7
// speedup vs baseline: 2.6076x; 2.6076x over previous
#include <cuda_runtime.h>

#define B_ 2
#define N_ 4096
#define M_ 4096
#define K_ 2048
#define NN 8192          // B_*N_ flattened points
#define KTOP 50
#define CAND_CAP 3072

static __device__ unsigned g_min_pg[B_*N_];   // min over gt for each pred
static __device__ unsigned g_min_gp[B_*M_];   // min over pred for each gt
static __device__ unsigned g_min_cov[B_*K_];  // min over pred for each partial
static __device__ double   g_acc[8];          // 0:cham1 1:cham2 2:cov 3:emd 4:unif 5:spread 6:rep
static __device__ float4   g_pts4[NN];        // packed pred points for uniformity
static __device__ float    g_sortP[3*NN];
static __device__ float    g_sortG[3*NN];

// ---------------------------------------------------------------- helpers
__device__ __forceinline__ void block_add_to_acc(float v, int slot) {
    for (int o = 16; o; o >>= 1) v += __shfl_xor_sync(0xFFFFFFFFu, v, o);
    __shared__ float sw[32];
    int lane = threadIdx.x & 31, wid = threadIdx.x >> 5;
    if (lane == 0) sw[wid] = v;
    __syncthreads();
    if (threadIdx.x == 0) {
        float s = 0.f;
        int nw = (blockDim.x + 31) >> 5;
        for (int w = 0; w < nw; w++) s += sw[w];
        atomicAdd(&g_acc[slot], (double)s);
    }
}

__device__ __forceinline__ unsigned* min_sel(int which) {
    return which == 0 ? g_min_pg : (which == 1 ? g_min_gp : g_min_cov);
}

// ---------------------------------------------------------------- init + pack (fused)
__global__ void initpack_kernel(const float* __restrict__ pred) {
    int i = blockIdx.x * 256 + threadIdx.x;
    if (i < B_*N_) g_min_pg[i]  = 0x7F800000u;
    if (i < B_*M_) g_min_gp[i]  = 0x7F800000u;
    if (i < B_*K_) g_min_cov[i] = 0x7F800000u;
    if (i < 8)     g_acc[i] = 0.0;
    if (i < NN)    g_pts4[i] = make_float4(pred[3*i], pred[3*i+1], pred[3*i+2], 0.f);
}

// ---------------------------------------------------------------- row-min pairwise sq dist
// Each thread owns TWO A points (i and i+128); scans B points staged in smem.
// Sharing each staged B point across 2 A points halves LDS traffic (was L1-bound).
__global__ void rowmin_kernel(const float* __restrict__ A, const float* __restrict__ Bp,
                              int nA, int nB, int chunk, int which) {
    __shared__ float sb[384];
    int b = blockIdx.z;
    const float* Ab = A  + (size_t)b * nA * 3;
    const float* Bb = Bp + ((size_t)b * nB + (size_t)blockIdx.y * chunk) * 3;
    int i0 = blockIdx.x * 256 + threadIdx.x;
    int i1 = i0 + 128;
    float ax0 = Ab[3*i0], ay0 = Ab[3*i0+1], az0 = Ab[3*i0+2];
    float ax1 = Ab[3*i1], ay1 = Ab[3*i1+1], az1 = Ab[3*i1+2];
    float best0 = __int_as_float(0x7F800000);
    float best1 = best0;
    for (int t = 0; t < chunk; t += 128) {
        __syncthreads();
        const float* src = Bb + 3*t;
        sb[threadIdx.x]       = src[threadIdx.x];
        sb[threadIdx.x + 128] = src[threadIdx.x + 128];
        sb[threadIdx.x + 256] = src[threadIdx.x + 256];
        __syncthreads();
#pragma unroll 8
        for (int j = 0; j < 128; j++) {
            float qx = sb[3*j], qy = sb[3*j+1], qz = sb[3*j+2];
            float dx0 = ax0 - qx, dy0 = ay0 - qy, dz0 = az0 - qz;
            float dx1 = ax1 - qx, dy1 = ay1 - qy, dz1 = az1 - qz;
            float dd0 = fmaf(dx0, dx0, fmaf(dy0, dy0, dz0*dz0));
            float dd1 = fmaf(dx1, dx1, fmaf(dy1, dy1, dz1*dz1));
            best0 = fminf(best0, dd0);
            best1 = fminf(best1, dd1);
        }
    }
    unsigned* dst = min_sel(which);
    atomicMin(&dst[b*nA + i0], __float_as_uint(best0));
    atomicMin(&dst[b*nA + i1], __float_as_uint(best1));
}

// ---------------------------------------------------------------- fused sum-of-mins
// blocks [0,32): pg slot0 | [32,64): gp slot1 | [64,80): cov slot2 (sqrt)
__global__ void summin_all_kernel() {
    int blk = blockIdx.x;
    float v;
    if (blk < 32) {
        v = __uint_as_float(g_min_pg[blk*256 + threadIdx.x]);
        block_add_to_acc(v, 0);
    } else if (blk < 64) {
        v = __uint_as_float(g_min_gp[(blk-32)*256 + threadIdx.x]);
        block_add_to_acc(v, 1);
    } else {
        v = sqrtf(__uint_as_float(g_min_cov[(blk-64)*256 + threadIdx.x]));
        block_add_to_acc(v, 2);
    }
}

// ---------------------------------------------------------------- EMD: bitonic column sort
__global__ void emd_sort_kernel(const float* __restrict__ pred, const float* __restrict__ gt) {
    __shared__ float a[NN];
    int which = blockIdx.x;           // 0..5
    int c = which % 3;
    const float* src = (which < 3) ? pred : gt;
    float* dst = (which < 3) ? (g_sortP + c*NN) : (g_sortG + c*NN);
    int tid = threadIdx.x;
    for (int i = tid; i < NN; i += 1024) a[i] = src[3*i + c];
    __syncthreads();
    for (int k = 2; k <= NN; k <<= 1)
        for (int j = k >> 1; j > 0; j >>= 1) {
            for (int i = tid; i < NN; i += 1024) {
                int ixj = i ^ j;
                if (ixj > i) {
                    float x = a[i], y = a[ixj];
                    bool up = ((i & k) == 0);
                    if ((x > y) == up) { a[i] = y; a[ixj] = x; }
                }
            }
            __syncthreads();
        }
    for (int i = tid; i < NN; i += 1024) dst[i] = a[i];
}

__global__ void emd_diff_kernel() {
    int i = blockIdx.x * 256 + threadIdx.x;
    float v = 0.f;
    if (i < 3*NN) { float d = g_sortP[i] - g_sortG[i]; v = d*d; }
    block_add_to_acc(v, 3);
}

// ---------------------------------------------------------------- uniformity: per-row 50-NN std
// (proven R4 version) Block handles 32 rows; distances in registers (32/thread).
// Exact top-50: exponent-bucket histogram -> candidate gather -> parallel rank-by-count.
__global__ void __launch_bounds__(256) uniformity_kernel() {
    __shared__ float    s_buf[CAND_CAP];
    __shared__ unsigned s_hist[256];
    __shared__ unsigned s_cnt;
    __shared__ unsigned s_E;
    __shared__ float    s_r1[8], s_r2[8];
    int tid = threadIdx.x, lane = tid & 31, wid = tid >> 5;
    double rowacc = 0.0;   // meaningful only on tid==0

    for (int r = 0; r < 32; r++) {
        int row = blockIdx.x * 32 + r;
        float4 p = g_pts4[row];
        s_hist[tid] = 0;
        if (tid == 0) s_cnt = 0;
        __syncthreads();

        float d[32];
#pragma unroll
        for (int k = 0; k < 32; k++) {
            float4 q = g_pts4[k*256 + tid];
            float dx = p.x - q.x, dy = p.y - q.y, dz = p.z - q.z;
            d[k] = fmaf(dx, dx, fmaf(dy, dy, dz*dz));
        }
        // exponent-bucket histogram with warp aggregation
#pragma unroll
        for (int k = 0; k < 32; k++) {
            unsigned bin = __float_as_uint(d[k]) >> 23;
            unsigned mask = __match_any_sync(0xFFFFFFFFu, bin);
            int leader = __ffs(mask) - 1;
            if (lane == leader) atomicAdd(&s_hist[bin], (unsigned)__popc(mask));
        }
        __syncthreads();
        // warp 0: find smallest bucket E with cumulative count >= KTOP
        if (wid == 0) {
            unsigned v[8], loc = 0;
#pragma unroll
            for (int b2 = 0; b2 < 8; b2++) { v[b2] = s_hist[lane*8 + b2]; loc += v[b2]; }
            unsigned pre = loc;
            for (int o = 1; o < 32; o <<= 1) {
                unsigned t2 = __shfl_up_sync(0xFFFFFFFFu, pre, o);
                if (lane >= o) pre += t2;
            }
            unsigned cum = pre - loc;
            int myE = 256;
#pragma unroll
            for (int b2 = 0; b2 < 8; b2++) {
                cum += v[b2];
                if ((int)cum >= KTOP && myE == 256) myE = lane*8 + b2;
            }
            for (int o = 16; o; o >>= 1) {
                int t3 = __shfl_xor_sync(0xFFFFFFFFu, myE, o);
                myE = min(myE, t3);
            }
            if (lane == 0) s_E = (unsigned)myE;
        }
        __syncthreads();
        unsigned E = s_E;
        // gather candidates
#pragma unroll
        for (int k = 0; k < 32; k++) {
            unsigned bin = __float_as_uint(d[k]) >> 23;
            if (bin <= E) {
                unsigned pos = atomicAdd(&s_cnt, 1u);
                if (pos < CAND_CAP) s_buf[pos] = d[k];
            }
        }
        __syncthreads();
        // parallel exact selection: rank each candidate by counting
        int c = (int)min(s_cnt, (unsigned)CAND_CAP);
        float t1 = 0.f, t2 = 0.f;
        for (int j = tid; j < c; j += 256) {
            float v = s_buf[j];
            int rank = 0;
            for (int k = 0; k < c; k++) {
                float w = s_buf[k];
                rank += (w < v) || (w == v && k < j);
            }
            if (rank >= 1 && rank < KTOP) { t1 += sqrtf(v); t2 += v; }
        }
        // block reduce (t1, t2)
        for (int o = 16; o; o >>= 1) {
            t1 += __shfl_xor_sync(0xFFFFFFFFu, t1, o);
            t2 += __shfl_xor_sync(0xFFFFFFFFu, t2, o);
        }
        if (lane == 0) { s_r1[wid] = t1; s_r2[wid] = t2; }
        __syncthreads();
        if (tid == 0) {
            double s1 = 0.0, s2 = 0.0;
            for (int w = 0; w < 8; w++) { s1 += (double)s_r1[w]; s2 += (double)s_r2[w]; }
            double mean = s1 / 49.0;
            double var = (s2 - 49.0*mean*mean) / 48.0;
            if (var < 0.0) var = 0.0;
            rowacc += sqrt(var);
        }
        __syncthreads();
    }
    if (tid == 0) atomicAdd(&g_acc[4], rowacc);
}

// ---------------------------------------------------------------- spread + repulsion (fused)
// blocks 0..5: spread (b,c). block 6: repulsion.
__global__ void spreadrep_kernel(const float* __restrict__ pred,
                                 const int* __restrict__ sidx) {
    int tid = threadIdx.x;
    if (blockIdx.x < 6) {
        int b = blockIdx.x / 3, c = blockIdx.x % 3;
        const float* p = pred + (size_t)b * N_ * 3 + c;
        double s1 = 0.0, s2 = 0.0;
        for (int i = tid; i < N_; i += 256) {
            double x = (double)p[3*i];
            s1 += x; s2 += x*x;
        }
        for (int o = 16; o; o >>= 1) {
            s1 += __shfl_xor_sync(0xFFFFFFFFu, s1, o);
            s2 += __shfl_xor_sync(0xFFFFFFFFu, s2, o);
        }
        __shared__ double sw1[8], sw2[8];
        int lane = tid & 31, wid = tid >> 5;
        if (lane == 0) { sw1[wid] = s1; sw2[wid] = s2; }
        __syncthreads();
        if (tid == 0) {
            double a = 0, bb = 0;
            for (int w = 0; w < 8; w++) { a += sw1[w]; bb += sw2[w]; }
            double mean = a / (double)N_;
            double var = (bb - (double)N_ * mean * mean) / (double)(N_ - 1);
            if (var < 0.0) var = 0.0;
            atomicAdd(&g_acc[5], sqrt(var));
        }
    } else {
        // NOTE: sample_idx arrives as int32 (JAX x64 disabled downcasts astype(int64)).
        __shared__ float sp[200*3];
        for (int s = tid; s < 200; s += 256) {
            int b = s / 100, k = s % 100;
            int idx = sidx[k];
            if (idx < 0) idx = 0;
            if (idx >= N_) idx = N_ - 1;
            const float* src = pred + ((size_t)b * N_ + (size_t)idx) * 3;
            sp[3*s] = src[0]; sp[3*s+1] = src[1]; sp[3*s+2] = src[2];
        }
        __syncthreads();
        float sum = 0.f;
        for (int t = tid; t < 2*100*100; t += 256) {
            int b = t / 10000, rem = t % 10000, i = rem / 100, j = rem % 100;
            if (i != j) {
                const float* pi = &sp[(b*100 + i)*3];
                const float* pj = &sp[(b*100 + j)*3];
                float dx = pi[0]-pj[0], dy = pi[1]-pj[1], dz = pi[2]-pj[2];
                float dd = fmaf(dx, dx, fmaf(dy, dy, dz*dz));
                float rr = 0.01f - sqrtf(dd);
                if (rr > 0.f) sum += rr;
            }
        }
        block_add_to_acc(sum, 6);
    }
}

// ---------------------------------------------------------------- finalize
__global__ void final_kernel(float* out) {
    double cham   = g_acc[0] / (double)(B_*N_) + g_acc[1] / (double)(B_*M_);
    double emd    = g_acc[3] / (double)(NN*3) * 0.1;
    double cov    = g_acc[2] / (double)(B_*K_) * 5.0;
    double unif   = g_acc[4] / (double)NN * 2.0;
    double sstd   = g_acc[5] / 6.0;
    double spread = 0.5 - sstd;
    spread = (spread > 0.0) ? spread * 10.0 : 0.0;
    double rep    = g_acc[6] / (double)(B_*100*100) * 5.0;
    out[0] = (float)(cham + emd + cov + unif + spread + rep);
}

// ---------------------------------------------------------------- launch
// Serial single stream (multi-stream measured as regression in R5).
// Order chosen so the 6th launch (ncu -s 5 -c 1) is uniformity_kernel.
extern "C" void kernel_launch(void* const* d_in, const int* in_sizes, int n_in,
                              void* d_out, int out_size) {
    const float* pred    = (const float*)d_in[0];
    const float* gt      = (const float*)d_in[1];
    const float* partial = (const float*)d_in[2];
    const int*   sidx    = (const int*)d_in[3];
    float* out = (float*)d_out;

    initpack_kernel<<<32, 256>>>(pred);                                          // 1

    rowmin_kernel<<<dim3(N_/256, 16, B_), 128>>>(pred, gt,   N_, M_, M_/16, 0);  // 2
    rowmin_kernel<<<dim3(M_/256, 16, B_), 128>>>(gt,   pred, M_, N_, N_/16, 1);  // 3
    rowmin_kernel<<<dim3(K_/256, 16, B_), 128>>>(partial, pred, K_, N_, N_/16, 2);// 4

    summin_all_kernel<<<80, 256>>>();                                            // 5

    uniformity_kernel<<<NN/32, 256>>>();                                         // 6 <- profiled

    emd_sort_kernel<<<6, 1024>>>(pred, gt);                                      // 7
    emd_diff_kernel<<<(3*NN+255)/256, 256>>>();                                  // 8

    spreadrep_kernel<<<7, 256>>>(pred, sidx);                                    // 9

    final_kernel<<<1, 1>>>(out);                                                 // 10
}

// round 9
// speedup vs baseline: 2.9595x; 1.1350x over previous
#include <cuda_runtime.h>

#define B_ 2
#define N_ 4096
#define M_ 4096
#define K_ 2048
#define NN 8192          // B_*N_ flattened points
#define KTOP 50
#define CAND_CAP 2048
#define FINE_CAP 128

static __device__ unsigned g_min_pg[B_*N_];   // min over gt for each pred
static __device__ unsigned g_min_gp[B_*M_];   // min over pred for each gt
static __device__ unsigned g_min_cov[B_*K_];  // min over pred for each partial
static __device__ double   g_acc[8];          // 0:cham1 1:cham2 2:cov 3:emd 4:unif 5:spread 6:rep
static __device__ float4   g_pts4[NN];        // packed pred points for uniformity
static __device__ float    g_sortP[3*NN];
static __device__ float    g_sortG[3*NN];

// ---------------------------------------------------------------- helpers
__device__ __forceinline__ void block_add_to_acc(float v, int slot) {
    for (int o = 16; o; o >>= 1) v += __shfl_xor_sync(0xFFFFFFFFu, v, o);
    __shared__ float sw[32];
    int lane = threadIdx.x & 31, wid = threadIdx.x >> 5;
    if (lane == 0) sw[wid] = v;
    __syncthreads();
    if (threadIdx.x == 0) {
        float s = 0.f;
        int nw = (blockDim.x + 31) >> 5;
        for (int w = 0; w < nw; w++) s += sw[w];
        atomicAdd(&g_acc[slot], (double)s);
    }
}

__device__ __forceinline__ unsigned* min_sel(int which) {
    return which == 0 ? g_min_pg : (which == 1 ? g_min_gp : g_min_cov);
}

// warp0 collective: over 256-bin histogram h, find first bin where cumulative
// count >= target; out[0]=bin, out[1]=cumulative count strictly below that bin.
__device__ __forceinline__ void warp0_find(const unsigned* h, int target,
                                           unsigned* out, int lane) {
    unsigned v8[8], loc = 0;
#pragma unroll
    for (int b = 0; b < 8; b++) { v8[b] = h[lane*8 + b]; loc += v8[b]; }
    unsigned pre = loc;
    for (int o = 1; o < 32; o <<= 1) {
        unsigned t = __shfl_up_sync(0xFFFFFFFFu, pre, o);
        if (lane >= o) pre += t;
    }
    unsigned cum = pre - loc;          // exclusive prefix
    int myBin = 256; unsigned myBelow = 0;
#pragma unroll
    for (int b = 0; b < 8; b++) {
        unsigned nb = cum + v8[b];
        if ((int)nb >= target && myBin == 256) { myBin = lane*8 + b; myBelow = cum; }
        cum = nb;
    }
    for (int o = 16; o; o >>= 1) {
        int ob = __shfl_xor_sync(0xFFFFFFFFu, myBin, o);
        unsigned obl = __shfl_xor_sync(0xFFFFFFFFu, myBelow, o);
        if (ob < myBin) { myBin = ob; myBelow = obl; }
    }
    if (lane == 0) { out[0] = (unsigned)myBin; out[1] = myBelow; }
}

// ---------------------------------------------------------------- init + pack (fused)
__global__ void initpack_kernel(const float* __restrict__ pred) {
    int i = blockIdx.x * 256 + threadIdx.x;
    if (i < B_*N_) g_min_pg[i]  = 0x7F800000u;
    if (i < B_*M_) g_min_gp[i]  = 0x7F800000u;
    if (i < B_*K_) g_min_cov[i] = 0x7F800000u;
    if (i < 8)     g_acc[i] = 0.0;
    if (i < NN)    g_pts4[i] = make_float4(pred[3*i], pred[3*i+1], pred[3*i+2], 0.f);
}

// ---------------------------------------------------------------- row-min pairwise sq dist
// Each thread owns TWO A points (i and i+128); scans B points staged in smem.
__global__ void rowmin_kernel(const float* __restrict__ A, const float* __restrict__ Bp,
                              int nA, int nB, int chunk, int which) {
    __shared__ float sb[384];
    int b = blockIdx.z;
    const float* Ab = A  + (size_t)b * nA * 3;
    const float* Bb = Bp + ((size_t)b * nB + (size_t)blockIdx.y * chunk) * 3;
    int i0 = blockIdx.x * 256 + threadIdx.x;
    int i1 = i0 + 128;
    float ax0 = Ab[3*i0], ay0 = Ab[3*i0+1], az0 = Ab[3*i0+2];
    float ax1 = Ab[3*i1], ay1 = Ab[3*i1+1], az1 = Ab[3*i1+2];
    float best0 = __int_as_float(0x7F800000);
    float best1 = best0;
    for (int t = 0; t < chunk; t += 128) {
        __syncthreads();
        const float* src = Bb + 3*t;
        sb[threadIdx.x]       = src[threadIdx.x];
        sb[threadIdx.x + 128] = src[threadIdx.x + 128];
        sb[threadIdx.x + 256] = src[threadIdx.x + 256];
        __syncthreads();
#pragma unroll 8
        for (int j = 0; j < 128; j++) {
            float qx = sb[3*j], qy = sb[3*j+1], qz = sb[3*j+2];
            float dx0 = ax0 - qx, dy0 = ay0 - qy, dz0 = az0 - qz;
            float dx1 = ax1 - qx, dy1 = ay1 - qy, dz1 = az1 - qz;
            float dd0 = fmaf(dx0, dx0, fmaf(dy0, dy0, dz0*dz0));
            float dd1 = fmaf(dx1, dx1, fmaf(dy1, dy1, dz1*dz1));
            best0 = fminf(best0, dd0);
            best1 = fminf(best1, dd1);
        }
    }
    unsigned* dst = min_sel(which);
    atomicMin(&dst[b*nA + i0], __float_as_uint(best0));
    atomicMin(&dst[b*nA + i1], __float_as_uint(best1));
}

// ---------------------------------------------------------------- fused sum-of-mins
__global__ void summin_all_kernel() {
    int blk = blockIdx.x;
    float v;
    if (blk < 32) {
        v = __uint_as_float(g_min_pg[blk*256 + threadIdx.x]);
        block_add_to_acc(v, 0);
    } else if (blk < 64) {
        v = __uint_as_float(g_min_gp[(blk-32)*256 + threadIdx.x]);
        block_add_to_acc(v, 1);
    } else {
        v = sqrtf(__uint_as_float(g_min_cov[(blk-64)*256 + threadIdx.x]));
        block_add_to_acc(v, 2);
    }
}

// ---------------------------------------------------------------- EMD: bitonic column sort
__global__ void emd_sort_kernel(const float* __restrict__ pred, const float* __restrict__ gt) {
    __shared__ float a[NN];
    int which = blockIdx.x;           // 0..5
    int c = which % 3;
    const float* src = (which < 3) ? pred : gt;
    float* dst = (which < 3) ? (g_sortP + c*NN) : (g_sortG + c*NN);
    int tid = threadIdx.x;
    for (int i = tid; i < NN; i += 1024) a[i] = src[3*i + c];
    __syncthreads();
    for (int k = 2; k <= NN; k <<= 1)
        for (int j = k >> 1; j > 0; j >>= 1) {
            for (int i = tid; i < NN; i += 1024) {
                int ixj = i ^ j;
                if (ixj > i) {
                    float x = a[i], y = a[ixj];
                    bool up = ((i & k) == 0);
                    if ((x > y) == up) { a[i] = y; a[ixj] = x; }
                }
            }
            __syncthreads();
        }
    for (int i = tid; i < NN; i += 1024) dst[i] = a[i];
}

__global__ void emd_diff_kernel() {
    int i = blockIdx.x * 256 + threadIdx.x;
    float v = 0.f;
    if (i < 3*NN) { float d = g_sortP[i] - g_sortG[i]; v = d*d; }
    block_add_to_acc(v, 3);
}

// ---------------------------------------------------------------- uniformity: per-row 50-NN std
// Exact top-50 sum without full ranking:
//   exponent histogram -> bucket E (first with cum>=50): bins < E summed directly;
//   bucket-E members get a mantissa-bit fine histogram -> fine bins < F summed
//   directly; only the boundary fine bin (couple of elements) is micro-ranked.
// Self-distance 0 contributes 0 to both sums, so top-50 sum == ranks 1..49 sum.
__global__ void __launch_bounds__(256) uniformity_kernel() {
    __shared__ float    s_buf[CAND_CAP];
    __shared__ float    s_buf2[FINE_CAP];
    __shared__ unsigned s_hist[512];        // [0,256): exponent, [256,512): fine
    __shared__ unsigned s_cnt, s_cnt2;
    __shared__ unsigned s_sel[2], s_sel2[2];
    __shared__ float    s_r1[8], s_r2[8];
    int tid = threadIdx.x, lane = tid & 31, wid = tid >> 5;
    double rowacc = 0.0;   // meaningful only on tid==0

    for (int r = 0; r < 32; r++) {
        int row = blockIdx.x * 32 + r;
        float4 p = g_pts4[row];
        s_hist[tid] = 0; s_hist[tid + 256] = 0;
        if (tid == 0) { s_cnt = 0; s_cnt2 = 0; }
        __syncthreads();

        float d[32];
#pragma unroll
        for (int k = 0; k < 32; k++) {
            float4 q = g_pts4[k*256 + tid];
            float dx = p.x - q.x, dy = p.y - q.y, dz = p.z - q.z;
            d[k] = fmaf(dx, dx, fmaf(dy, dy, dz*dz));
        }
        // exponent-bucket histogram with warp aggregation
#pragma unroll
        for (int k = 0; k < 32; k++) {
            unsigned bin = __float_as_uint(d[k]) >> 23;
            unsigned mask = __match_any_sync(0xFFFFFFFFu, bin);
            int leader = __ffs(mask) - 1;
            if (lane == leader) atomicAdd(&s_hist[bin], (unsigned)__popc(mask));
        }
        __syncthreads();
        if (wid == 0) warp0_find(s_hist, KTOP, s_sel, lane);
        __syncthreads();
        unsigned E = s_sel[0];
        int m = KTOP - (int)s_sel[1];          // how many needed from bucket E (>=1)

        float t1 = 0.f, t2 = 0.f;
        // gather: bins < E contribute directly; bin == E goes to refinement buffer
#pragma unroll
        for (int k = 0; k < 32; k++) {
            float v = d[k];
            unsigned bin = __float_as_uint(v) >> 23;
            if (bin < E) { t1 += sqrtf(v); t2 += v; }
            else if (bin == E) {
                unsigned pos = atomicAdd(&s_cnt, 1u);
                if (pos < CAND_CAP) s_buf[pos] = v;
            }
        }
        __syncthreads();
        int cE = (int)min(s_cnt, (unsigned)CAND_CAP);
        // fine histogram on top-8 mantissa bits (same exponent => monotone)
        for (int j = tid; j < cE; j += 256)
            atomicAdd(&s_hist[256 + ((__float_as_uint(s_buf[j]) >> 15) & 0xFFu)], 1u);
        __syncthreads();
        if (wid == 0) warp0_find(s_hist + 256, m, s_sel2, lane);
        __syncthreads();
        unsigned F = s_sel2[0];
        int m2 = m - (int)s_sel2[1];           // needed from fine bin F (>=1)
        // second pass over bucket-E members
        for (int j = tid; j < cE; j += 256) {
            float v = s_buf[j];
            unsigned key = (__float_as_uint(v) >> 15) & 0xFFu;
            if (key < F) { t1 += sqrtf(v); t2 += v; }
            else if (key == F) {
                unsigned pos = atomicAdd(&s_cnt2, 1u);
                if (pos < FINE_CAP) s_buf2[pos] = v;
            }
        }
        __syncthreads();
        int cF = (int)min(s_cnt2, (unsigned)FINE_CAP);
        // micro-rank boundary fine bin, take the m2 smallest (index tiebreak)
        for (int j = tid; j < cF; j += 256) {
            float v = s_buf2[j];
            int rank = 0;
            for (int k = 0; k < cF; k++) {
                float w = s_buf2[k];
                rank += (w < v) || (w == v && k < j);
            }
            if (rank < m2) { t1 += sqrtf(v); t2 += v; }
        }
        // block reduce (t1, t2)
        for (int o = 16; o; o >>= 1) {
            t1 += __shfl_xor_sync(0xFFFFFFFFu, t1, o);
            t2 += __shfl_xor_sync(0xFFFFFFFFu, t2, o);
        }
        if (lane == 0) { s_r1[wid] = t1; s_r2[wid] = t2; }
        __syncthreads();
        if (tid == 0) {
            double s1 = 0.0, s2 = 0.0;
            for (int w = 0; w < 8; w++) { s1 += (double)s_r1[w]; s2 += (double)s_r2[w]; }
            double mean = s1 / 49.0;
            double var = (s2 - 49.0*mean*mean) / 48.0;
            if (var < 0.0) var = 0.0;
            rowacc += sqrt(var);
        }
        __syncthreads();
    }
    if (tid == 0) atomicAdd(&g_acc[4], rowacc);
}

// ---------------------------------------------------------------- spread + repulsion (fused)
__global__ void spreadrep_kernel(const float* __restrict__ pred,
                                 const int* __restrict__ sidx) {
    int tid = threadIdx.x;
    if (blockIdx.x < 6) {
        int b = blockIdx.x / 3, c = blockIdx.x % 3;
        const float* p = pred + (size_t)b * N_ * 3 + c;
        double s1 = 0.0, s2 = 0.0;
        for (int i = tid; i < N_; i += 256) {
            double x = (double)p[3*i];
            s1 += x; s2 += x*x;
        }
        for (int o = 16; o; o >>= 1) {
            s1 += __shfl_xor_sync(0xFFFFFFFFu, s1, o);
            s2 += __shfl_xor_sync(0xFFFFFFFFu, s2, o);
        }
        __shared__ double sw1[8], sw2[8];
        int lane = tid & 31, wid = tid >> 5;
        if (lane == 0) { sw1[wid] = s1; sw2[wid] = s2; }
        __syncthreads();
        if (tid == 0) {
            double a = 0, bb = 0;
            for (int w = 0; w < 8; w++) { a += sw1[w]; bb += sw2[w]; }
            double mean = a / (double)N_;
            double var = (bb - (double)N_ * mean * mean) / (double)(N_ - 1);
            if (var < 0.0) var = 0.0;
            atomicAdd(&g_acc[5], sqrt(var));
        }
    } else {
        // NOTE: sample_idx arrives as int32 (JAX x64 disabled downcasts astype(int64)).
        __shared__ float sp[200*3];
        for (int s = tid; s < 200; s += 256) {
            int b = s / 100, k = s % 100;
            int idx = sidx[k];
            if (idx < 0) idx = 0;
            if (idx >= N_) idx = N_ - 1;
            const float* src = pred + ((size_t)b * N_ + (size_t)idx) * 3;
            sp[3*s] = src[0]; sp[3*s+1] = src[1]; sp[3*s+2] = src[2];
        }
        __syncthreads();
        float sum = 0.f;
        for (int t = tid; t < 2*100*100; t += 256) {
            int b = t / 10000, rem = t % 10000, i = rem / 100, j = rem % 100;
            if (i != j) {
                const float* pi = &sp[(b*100 + i)*3];
                const float* pj = &sp[(b*100 + j)*3];
                float dx = pi[0]-pj[0], dy = pi[1]-pj[1], dz = pi[2]-pj[2];
                float dd = fmaf(dx, dx, fmaf(dy, dy, dz*dz));
                float rr = 0.01f - sqrtf(dd);
                if (rr > 0.f) sum += rr;
            }
        }
        block_add_to_acc(sum, 6);
    }
}

// ---------------------------------------------------------------- finalize
__global__ void final_kernel(float* out) {
    double cham   = g_acc[0] / (double)(B_*N_) + g_acc[1] / (double)(B_*M_);
    double emd    = g_acc[3] / (double)(NN*3) * 0.1;
    double cov    = g_acc[2] / (double)(B_*K_) * 5.0;
    double unif   = g_acc[4] / (double)NN * 2.0;
    double sstd   = g_acc[5] / 6.0;
    double spread = 0.5 - sstd;
    spread = (spread > 0.0) ? spread * 10.0 : 0.0;
    double rep    = g_acc[6] / (double)(B_*100*100) * 5.0;
    out[0] = (float)(cham + emd + cov + unif + spread + rep);
}

// ---------------------------------------------------------------- launch
// Main chain serial on stream 0; only the 6-block EMD branch overlaps on s2
// (R5 showed overlapping the chip-filling kernels regresses; emd is tiny-grid).
extern "C" void kernel_launch(void* const* d_in, const int* in_sizes, int n_in,
                              void* d_out, int out_size) {
    const float* pred    = (const float*)d_in[0];
    const float* gt      = (const float*)d_in[1];
    const float* partial = (const float*)d_in[2];
    const int*   sidx    = (const int*)d_in[3];
    float* out = (float*)d_out;

    static cudaStream_t s2 = 0;
    static cudaEvent_t  evRoot = 0, ev2 = 0;
    if (s2 == 0) {
        cudaStreamCreateWithFlags(&s2, cudaStreamNonBlocking);
        cudaEventCreateWithFlags(&evRoot, cudaEventDisableTiming);
        cudaEventCreateWithFlags(&ev2, cudaEventDisableTiming);
    }

    initpack_kernel<<<32, 256>>>(pred);                                           // 1
    cudaEventRecord(evRoot, 0);
    cudaStreamWaitEvent(s2, evRoot, 0);

    rowmin_kernel<<<dim3(N_/256, 16, B_), 128>>>(pred, gt,   N_, M_, M_/16, 0);   // 2
    rowmin_kernel<<<dim3(M_/256, 16, B_), 128>>>(gt,   pred, M_, N_, N_/16, 1);   // 3
    uniformity_kernel<<<NN/32, 256>>>();                                          // 4 <- profiled

    emd_sort_kernel<<<6, 1024, 0, s2>>>(pred, gt);                                // s2
    emd_diff_kernel<<<(3*NN+255)/256, 256, 0, s2>>>();                            // s2
    cudaEventRecord(ev2, s2);

    rowmin_kernel<<<dim3(K_/256, 16, B_), 128>>>(partial, pred, K_, N_, N_/16, 2);
    summin_all_kernel<<<80, 256>>>();
    spreadrep_kernel<<<7, 256>>>(pred, sidx);

    cudaStreamWaitEvent(0, ev2, 0);
    final_kernel<<<1, 1>>>(out);
}